// round 13
// baseline (speedup 1.0000x reference)
#include <cuda_runtime.h>
#include <math.h>

#define T_STEPS 4096
#define BATCH   32
#define DIN     256
#define HID     256
#define GATES   1024
#define OUTD    512
#define CL_SZ   8
#define NBLK    128

__device__ float g_xz_f[(size_t)T_STEPS * BATCH * GATES];
__device__ float g_xz_b[(size_t)T_STEPS * BATCH * GATES];
__device__ float g_houts[(size_t)T_STEPS * BATCH * 2 * HID];

__device__ __forceinline__ float sigf(float x)  { return 1.0f / (1.0f + __expf(-x)); }
__device__ __forceinline__ float tanhf_(float x){ return 1.0f - 2.0f / (__expf(2.0f * x) + 1.0f); }

__device__ __forceinline__ unsigned long long ffma2(
    unsigned long long a, unsigned long long b, unsigned long long c) {
    unsigned long long d;
    asm("fma.rn.f32x2 %0, %1, %2, %3;" : "=l"(d) : "l"(a), "l"(b), "l"(c));
    return d;
}
__device__ __forceinline__ unsigned long long bcast2(float a) {
    unsigned long long d;
    asm("mov.b64 %0, {%1, %1};" : "=l"(d) : "f"(a));
    return d;
}
__device__ __forceinline__ unsigned long long packf2(float lo, float hi) {
    unsigned long long d;
    asm("mov.b64 %0, {%1, %2};" : "=l"(d) : "f"(lo), "f"(hi));
    return d;
}
__device__ __forceinline__ unsigned smem_u32(const void* p) {
    return (unsigned)__cvta_generic_to_shared(p);
}
__device__ __forceinline__ void mbar_wait_cl(unsigned addr, unsigned parity) {
    asm volatile(
        "{\n\t.reg .pred P;\n"
        "LW%=:\n\t"
        "mbarrier.try_wait.parity.acquire.cluster.shared::cta.b64 P, [%0], %1, 0x989680;\n\t"
        "@P bra LD%=;\n\t"
        "bra LW%=;\n"
        "LD%=:\n\t}"
        :: "r"(addr), "r"(parity) : "memory");
}

#define CLUSTER_SYNC() do { \
    asm volatile("barrier.cluster.arrive.aligned;" ::: "memory"); \
    asm volatile("barrier.cluster.wait.aligned;"   ::: "memory"); \
} while (0)

// ---------------- GEMM 1: xz = x @ Wx + bias (unchanged, passing) -----------
__global__ void __launch_bounds__(256) k_gemm_xz(
    const float* __restrict__ A, const float* __restrict__ W,
    const float* __restrict__ bias, float* __restrict__ C)
{
    __shared__ float As[8][128];
    __shared__ float Bs[8][128];
    const int tid = threadIdx.x;
    const int n0 = blockIdx.x << 7, m0 = blockIdx.y << 7;
    const int am = tid >> 1, ak = (tid & 1) << 2;
    const int bk = tid >> 5, bn = (tid & 31) << 2;
    const int ty = tid >> 4, tx = tid & 15;
    unsigned long long acc2[8][4] = {};

    for (int k0 = 0; k0 < DIN; k0 += 8) {
        float4 av = *(const float4*)(A + (size_t)(m0 + am) * DIN + k0 + ak);
        float4 bv = *(const float4*)(W + (size_t)(k0 + bk) * GATES + n0 + bn);
        __syncthreads();
        As[ak + 0][am] = av.x; As[ak + 1][am] = av.y;
        As[ak + 2][am] = av.z; As[ak + 3][am] = av.w;
        *(float4*)&Bs[bk][bn] = bv;
        __syncthreads();
#pragma unroll
        for (int kk = 0; kk < 8; kk++) {
            float ar[8];
            *(float4*)&ar[0] = *(const float4*)&As[kk][(ty << 3) + 0];
            *(float4*)&ar[4] = *(const float4*)&As[kk][(ty << 3) + 4];
            union { float4 f; unsigned long long u[2]; } B0, B1;
            B0.f = *(const float4*)&Bs[kk][(tx << 3) + 0];
            B1.f = *(const float4*)&Bs[kk][(tx << 3) + 4];
#pragma unroll
            for (int r = 0; r < 8; r++) {
                unsigned long long a2 = bcast2(ar[r]);
                acc2[r][0] = ffma2(a2, B0.u[0], acc2[r][0]);
                acc2[r][1] = ffma2(a2, B0.u[1], acc2[r][1]);
                acc2[r][2] = ffma2(a2, B1.u[0], acc2[r][2]);
                acc2[r][3] = ffma2(a2, B1.u[1], acc2[r][3]);
            }
        }
    }
    float bi[8];
    *(float4*)&bi[0] = *(const float4*)(bias + n0 + (tx << 3) + 0);
    *(float4*)&bi[4] = *(const float4*)(bias + n0 + (tx << 3) + 4);
#pragma unroll
    for (int r = 0; r < 8; r++) {
        int m = m0 + (ty << 3) + r;
        int t = m & (T_STEPS - 1), b = m >> 12;
        float* dst = C + (size_t)(t * BATCH + b) * GATES + n0 + (tx << 3);
        union { unsigned long long u; float f[2]; } U;
        float o[8];
#pragma unroll
        for (int c4 = 0; c4 < 4; c4++) {
            U.u = acc2[r][c4];
            o[2 * c4 + 0] = U.f[0] + bi[2 * c4 + 0];
            o[2 * c4 + 1] = U.f[1] + bi[2 * c4 + 1];
        }
        *(float4*)(dst + 0) = *(float4*)&o[0];
        *(float4*)(dst + 4) = *(float4*)&o[4];
    }
}

// ---------------- GEMM 2: out = relu(h_cat) @ W_dense + b (unchanged) ------
__global__ void __launch_bounds__(256) k_gemm_dense(
    const float* __restrict__ W, const float* __restrict__ bias,
    float* __restrict__ out)
{
    __shared__ float As[8][128];
    __shared__ float Bs[8][128];
    const int tid = threadIdx.x;
    const int n0 = blockIdx.x << 7, m0 = blockIdx.y << 7;
    const int am = tid >> 1, ak = (tid & 1) << 2;
    const int bk = tid >> 5, bn = (tid & 31) << 2;
    const int ty = tid >> 4, tx = tid & 15;
    unsigned long long acc2[8][4] = {};

    for (int k0 = 0; k0 < 2 * HID; k0 += 8) {
        float4 av = *(const float4*)(g_houts + (size_t)(m0 + am) * (2 * HID) + k0 + ak);
        av.x = fmaxf(av.x, 0.f); av.y = fmaxf(av.y, 0.f);
        av.z = fmaxf(av.z, 0.f); av.w = fmaxf(av.w, 0.f);
        float4 bv = *(const float4*)(W + (size_t)(k0 + bk) * OUTD + n0 + bn);
        __syncthreads();
        As[ak + 0][am] = av.x; As[ak + 1][am] = av.y;
        As[ak + 2][am] = av.z; As[ak + 3][am] = av.w;
        *(float4*)&Bs[bk][bn] = bv;
        __syncthreads();
#pragma unroll
        for (int kk = 0; kk < 8; kk++) {
            float ar[8];
            *(float4*)&ar[0] = *(const float4*)&As[kk][(ty << 3) + 0];
            *(float4*)&ar[4] = *(const float4*)&As[kk][(ty << 3) + 4];
            union { float4 f; unsigned long long u[2]; } B0, B1;
            B0.f = *(const float4*)&Bs[kk][(tx << 3) + 0];
            B1.f = *(const float4*)&Bs[kk][(tx << 3) + 4];
#pragma unroll
            for (int r = 0; r < 8; r++) {
                unsigned long long a2 = bcast2(ar[r]);
                acc2[r][0] = ffma2(a2, B0.u[0], acc2[r][0]);
                acc2[r][1] = ffma2(a2, B0.u[1], acc2[r][1]);
                acc2[r][2] = ffma2(a2, B1.u[0], acc2[r][2]);
                acc2[r][3] = ffma2(a2, B1.u[1], acc2[r][3]);
            }
        }
    }
    float bi[8];
    *(float4*)&bi[0] = *(const float4*)(bias + n0 + (tx << 3) + 0);
    *(float4*)&bi[4] = *(const float4*)(bias + n0 + (tx << 3) + 4);
#pragma unroll
    for (int r = 0; r < 8; r++) {
        int m = m0 + (ty << 3) + r;
        int b = m & 31, t = m >> 5;
        float* dst = out + ((size_t)b * T_STEPS + t) * OUTD + n0 + (tx << 3);
        union { unsigned long long u; float f[2]; } U;
        float o[8];
#pragma unroll
        for (int c4 = 0; c4 < 4; c4++) {
            U.u = acc2[r][c4];
            o[2 * c4 + 0] = U.f[0] + bi[2 * c4 + 0];
            o[2 * c4 + 1] = U.f[1] + bi[2 * c4 + 1];
        }
        *(float4*)(dst + 0) = *(float4*)&o[0];
        *(float4*)(dst + 4) = *(float4*)&o[4];
    }
}

// ---------------- Recurrence: vectorized st.async exchange -----------------
// R10 structure (best: 22.9ms). Changes:
//  (1) st.async.v2.b64 (16B): producer lanes shfl-gather 4 consecutive h,
//      lanes 0-7 of each producer warp push 1 store per peer -> 128
//      mbarrier-completing transactions per CTA per step instead of 512.
//  (2) compute warps bar.arrive (non-blocking), only producer warps
//      bar.sync; p_s double-buffered by step parity.
__global__ void __cluster_dims__(CL_SZ, 1, 1) __launch_bounds__(512, 1) k_recur(
    const float* __restrict__ carry_c, const float* __restrict__ carry_h,
    const float* __restrict__ Wh_f, const float* __restrict__ Wh_b)
{
    __shared__ float h_s[2][2][HID];           // [buf][batch][k], buf stride 2048B
    __shared__ float p_s[2][4][2][128];        // [par][q][batch][col]
    __shared__ unsigned long long mb[2];

    const int tid   = threadIdx.x;
    const int rank  = blockIdx.x & (CL_SZ - 1);
    const int b0    = (blockIdx.x >> 3) << 1;
    const int jbase = rank << 5;

    const int q    = tid >> 7;                 // k-quarter
    const int col  = tid & 127;
    const int gate = col >> 5, jl = col & 31;
    const int gc   = (gate << 8) + jbase + jl;

    const bool isprod = (tid >= 448);          // warps 14-15
    const int  pt = tid - 448;
    const int  bp = pt >> 5, jp = pt & 31;     // batch, local h-col (=lane)
    const unsigned TXB = CL_SZ * 64u * 4u;     // 2048 B per exchange

    h_s[0][tid >> 8][tid & 255] =
        carry_h[(size_t)(b0 + (tid >> 8)) * HID + (tid & 255)];

    if (tid == 0) {
        asm volatile("mbarrier.init.shared.b64 [%0], %1;"
                     :: "r"(smem_u32(&mb[0])), "r"(1) : "memory");
        asm volatile("mbarrier.init.shared.b64 [%0], %1;"
                     :: "r"(smem_u32(&mb[1])), "r"(1) : "memory");
    }

    float c_reg = 0.f;
    unsigned rem_h[CL_SZ];    // peer addr of h_s[0][bp][jbase + 4*(jp&7)]
    unsigned rem_mb[CL_SZ];   // peer addr of mb[0]
    if (isprod) {
        c_reg = carry_c[(size_t)(b0 + bp) * HID + jbase + jp];
        unsigned lh = smem_u32(&h_s[0][bp][jbase + ((jp & 7) << 2)]);
        unsigned lm = smem_u32(&mb[0]);
#pragma unroll
        for (int p = 0; p < CL_SZ; p++) {
            asm("mapa.shared::cluster.u32 %0, %1, %2;"
                : "=r"(rem_h[p]) : "r"(lh), "r"(p));
            asm("mapa.shared::cluster.u32 %0, %1, %2;"
                : "=r"(rem_mb[p]) : "r"(lm), "r"(p));
        }
    }
    __syncthreads();
    CLUSTER_SYNC();   // h bufs + mbars visible cluster-wide before step 0

    const unsigned mb0a = smem_u32(&mb[0]);

    int gs = 0;
    for (int dir = 0; dir < 2; dir++) {
        const float* __restrict__ Wh = dir ? Wh_b : Wh_f;
        const float* __restrict__ xz = dir ? g_xz_b : g_xz_f;
        const int half = dir ? HID : 0;

        unsigned long long w2[32];
#pragma unroll
        for (int kk = 0; kk < 32; kk++) {
            union { float f[2]; unsigned long long u; } P;
            P.f[0] = Wh[(size_t)((q << 6) + 2 * kk + 0) * GATES + gc];
            P.f[1] = Wh[(size_t)((q << 6) + 2 * kk + 1) * GATES + gc];
            w2[kk] = P.u;
        }

        float xzp[4];
        if (isprod) {
            const int t0 = dir ? (T_STEPS - 1) : 0;
#pragma unroll
            for (int g = 0; g < 4; g++)
                xzp[g] = __ldcg(xz + ((size_t)t0 * BATCH + b0 + bp) * GATES
                                   + (g << 8) + jbase + jp);
        }

        for (int s = 0; s < T_STEPS; s++, gs++) {
            const int t   = dir ? (T_STEPS - 1 - s) : s;
            const int cur = gs & 1, nxt = cur ^ 1;
            const int par = gs & 1;

            if (gs > 0) {   // wait for exchange gs-1 (all 2048 B landed)
                const int e = gs - 1;
                mbar_wait_cl(mb0a + (unsigned)((e & 1) << 3),
                             (unsigned)((e >> 1) & 1));
            }
            if (tid == 448)
                asm volatile(
                    "mbarrier.arrive.expect_tx.shared.b64 _, [%0], %1;"
                    :: "r"(mb0a + (unsigned)((gs & 1) << 3)), "r"(TXB)
                    : "memory");

            // partials over this thread's 64-k quarter, both batches
            unsigned long long a0 = 0ull, a1 = 0ull;
            {
                const float4* h0 = (const float4*)&h_s[cur][0][q << 6];
                const float4* h1 = (const float4*)&h_s[cur][1][q << 6];
#pragma unroll
                for (int i = 0; i < 16; i++) {
                    union { float4 f; unsigned long long u[2]; } U0, U1;
                    U0.f = h0[i]; U1.f = h1[i];
                    a0 = ffma2(U0.u[0], w2[2 * i + 0], a0);
                    a0 = ffma2(U0.u[1], w2[2 * i + 1], a0);
                    a1 = ffma2(U1.u[0], w2[2 * i + 0], a1);
                    a1 = ffma2(U1.u[1], w2[2 * i + 1], a1);
                }
            }
            {
                union { unsigned long long u; float f[2]; } A0, A1;
                A0.u = a0; A1.u = a1;
                p_s[par][q][0][col] = A0.f[0] + A0.f[1];
                p_s[par][q][1][col] = A1.f[0] + A1.f[1];
            }

            if (!isprod) {
                // non-blocking arrive; next blocking point is the mbar wait
                asm volatile("bar.arrive 1, 512;" ::: "memory");
            } else {
                asm volatile("bar.sync 1, 512;" ::: "memory");
                float z[4];
#pragma unroll
                for (int g = 0; g < 4; g++) {
                    const int cc = (g << 5) + jp;
                    z[g] = xzp[g] + p_s[par][0][bp][cc] + p_s[par][1][bp][cc]
                                  + p_s[par][2][bp][cc] + p_s[par][3][bp][cc];
                }
                c_reg = fmaf(sigf(z[1]), c_reg, sigf(z[0]) * tanhf_(z[2]));
                const float h = sigf(z[3]) * tanhf_(c_reg);
                g_houts[((size_t)t * BATCH + b0 + bp) * (2 * HID)
                        + half + jbase + jp] = h;
                if (s + 1 < T_STEPS) {
                    const int tn = dir ? (T_STEPS - 2 - s) : (s + 1);
#pragma unroll
                    for (int g = 0; g < 4; g++)
                        xzp[g] = __ldcg(xz + ((size_t)tn * BATCH + b0 + bp) * GATES
                                           + (g << 8) + jbase + jp);
                }
                // gather 4 consecutive h within the producer warp (batch bp)
                const int m = jp & 7;
                const float h0 = __shfl_sync(0xffffffffu, h, (m << 2) + 0);
                const float h1 = __shfl_sync(0xffffffffu, h, (m << 2) + 1);
                const float h2 = __shfl_sync(0xffffffffu, h, (m << 2) + 2);
                const float h3 = __shfl_sync(0xffffffffu, h, (m << 2) + 3);
                if (jp < 8) {
                    const unsigned long long lo = packf2(h0, h1);
                    const unsigned long long hi = packf2(h2, h3);
                    const unsigned hoff = (unsigned)(nxt << 11);     // 2048 B
                    const unsigned moff = (unsigned)((gs & 1) << 3);
#pragma unroll
                    for (int p = 0; p < CL_SZ; p++)
                        asm volatile(
                            "st.async.shared::cluster.mbarrier::complete_tx::bytes"
                            ".v2.b64 [%0], {%1, %2}, [%3];"
                            :: "r"(rem_h[p] + hoff), "l"(lo), "l"(hi),
                               "r"(rem_mb[p] + moff) : "memory");
                }
            }
        }
    }
    // drain final exchange so no in-flight st.async targets exiting CTAs
    {
        const int e = 2 * T_STEPS - 1;
        mbar_wait_cl(mb0a + (unsigned)((e & 1) << 3), (unsigned)((e >> 1) & 1));
    }
    CLUSTER_SYNC();
}

// ---------------- launch ----------------------------------------------------
extern "C" void kernel_launch(void* const* d_in, const int* in_sizes, int n_in,
                              void* d_out, int out_size) {
    const float* carry_c = (const float*)d_in[0];
    const float* carry_h = (const float*)d_in[1];
    const float* x       = (const float*)d_in[2];
    const float* Wx_f    = (const float*)d_in[3];
    const float* Wh_f    = (const float*)d_in[4];
    const float* b_f     = (const float*)d_in[5];
    const float* Wx_b    = (const float*)d_in[6];
    const float* Wh_b    = (const float*)d_in[7];
    const float* b_b     = (const float*)d_in[8];
    const float* W_dense = (const float*)d_in[9];
    const float* b_dense = (const float*)d_in[10];
    float* out = (float*)d_out;

    float* xz_f; cudaGetSymbolAddress((void**)&xz_f, g_xz_f);
    float* xz_b; cudaGetSymbolAddress((void**)&xz_b, g_xz_b);

    dim3 g1(GATES / 128, (BATCH * T_STEPS) / 128);
    k_gemm_xz<<<g1, 256>>>(x, Wx_f, b_f, xz_f);
    k_gemm_xz<<<g1, 256>>>(x, Wx_b, b_b, xz_b);

    k_recur<<<NBLK, 512>>>(carry_c, carry_h, Wh_f, Wh_b);

    dim3 g2(OUTD / 128, (BATCH * T_STEPS) / 128);
    k_gemm_dense<<<g2, 256>>>(W_dense, b_dense, out);
}

// round 14
// speedup vs baseline: 1.2052x; 1.2052x over previous
#include <cuda_runtime.h>
#include <math.h>

#define T_STEPS 4096
#define BATCH   32
#define DIN     256
#define HID     256
#define GATES   1024
#define OUTD    512
#define CL_SZ   8
#define NBLK    128

__device__ float g_xz_f[(size_t)T_STEPS * BATCH * GATES];
__device__ float g_xz_b[(size_t)T_STEPS * BATCH * GATES];
__device__ float g_houts[(size_t)T_STEPS * BATCH * 2 * HID];

__device__ __forceinline__ float sigf(float x)  { return 1.0f / (1.0f + __expf(-x)); }
__device__ __forceinline__ float tanhf_(float x){ return 1.0f - 2.0f / (__expf(2.0f * x) + 1.0f); }

__device__ __forceinline__ unsigned long long ffma2(
    unsigned long long a, unsigned long long b, unsigned long long c) {
    unsigned long long d;
    asm("fma.rn.f32x2 %0, %1, %2, %3;" : "=l"(d) : "l"(a), "l"(b), "l"(c));
    return d;
}
__device__ __forceinline__ unsigned long long bcast2(float a) {
    unsigned long long d;
    asm("mov.b64 %0, {%1, %1};" : "=l"(d) : "f"(a));
    return d;
}
__device__ __forceinline__ unsigned smem_u32(const void* p) {
    return (unsigned)__cvta_generic_to_shared(p);
}

// Busy wait: test_wait poll + small FMA burn. Keeps every warp issuing work
// so the DVFS governor sees an active SM and holds boost clock. (try_wait's
// HW-sleep parks the warps -> near-idle SM -> clock drop; suspected cause of
// the flat ~2.1us/step across all protocol variants.)
__device__ __forceinline__ void mbar_wait_burn(unsigned addr, unsigned parity,
                                               float* bf) {
    while (true) {
        unsigned done;
        asm volatile(
            "{\n\t.reg .pred P;\n\t"
            "mbarrier.test_wait.parity.acquire.cluster.shared::cta.b64 P, [%1], %2;\n\t"
            "selp.b32 %0, 1, 0, P;\n\t}"
            : "=r"(done) : "r"(addr), "r"(parity) : "memory");
        if (done) break;
#pragma unroll
        for (int i = 0; i < 4; i++) {
            bf[0] = fmaf(bf[0], 1.0000001f, 1e-7f);
            bf[1] = fmaf(bf[1], 0.9999999f, 1e-7f);
            bf[2] = fmaf(bf[2], 1.0000002f, 1e-7f);
            bf[3] = fmaf(bf[3], 0.9999998f, 1e-7f);
        }
        asm volatile("" : "+f"(bf[0]), "+f"(bf[1]), "+f"(bf[2]), "+f"(bf[3]));
    }
}

#define CLUSTER_SYNC() do { \
    asm volatile("barrier.cluster.arrive.aligned;" ::: "memory"); \
    asm volatile("barrier.cluster.wait.aligned;"   ::: "memory"); \
} while (0)

// ---------------- GEMM 1: xz = x @ Wx + bias (unchanged, passing) -----------
__global__ void __launch_bounds__(256) k_gemm_xz(
    const float* __restrict__ A, const float* __restrict__ W,
    const float* __restrict__ bias, float* __restrict__ C)
{
    __shared__ float As[8][128];
    __shared__ float Bs[8][128];
    const int tid = threadIdx.x;
    const int n0 = blockIdx.x << 7, m0 = blockIdx.y << 7;
    const int am = tid >> 1, ak = (tid & 1) << 2;
    const int bk = tid >> 5, bn = (tid & 31) << 2;
    const int ty = tid >> 4, tx = tid & 15;
    unsigned long long acc2[8][4] = {};

    for (int k0 = 0; k0 < DIN; k0 += 8) {
        float4 av = *(const float4*)(A + (size_t)(m0 + am) * DIN + k0 + ak);
        float4 bv = *(const float4*)(W + (size_t)(k0 + bk) * GATES + n0 + bn);
        __syncthreads();
        As[ak + 0][am] = av.x; As[ak + 1][am] = av.y;
        As[ak + 2][am] = av.z; As[ak + 3][am] = av.w;
        *(float4*)&Bs[bk][bn] = bv;
        __syncthreads();
#pragma unroll
        for (int kk = 0; kk < 8; kk++) {
            float ar[8];
            *(float4*)&ar[0] = *(const float4*)&As[kk][(ty << 3) + 0];
            *(float4*)&ar[4] = *(const float4*)&As[kk][(ty << 3) + 4];
            union { float4 f; unsigned long long u[2]; } B0, B1;
            B0.f = *(const float4*)&Bs[kk][(tx << 3) + 0];
            B1.f = *(const float4*)&Bs[kk][(tx << 3) + 4];
#pragma unroll
            for (int r = 0; r < 8; r++) {
                unsigned long long a2 = bcast2(ar[r]);
                acc2[r][0] = ffma2(a2, B0.u[0], acc2[r][0]);
                acc2[r][1] = ffma2(a2, B0.u[1], acc2[r][1]);
                acc2[r][2] = ffma2(a2, B1.u[0], acc2[r][2]);
                acc2[r][3] = ffma2(a2, B1.u[1], acc2[r][3]);
            }
        }
    }
    float bi[8];
    *(float4*)&bi[0] = *(const float4*)(bias + n0 + (tx << 3) + 0);
    *(float4*)&bi[4] = *(const float4*)(bias + n0 + (tx << 3) + 4);
#pragma unroll
    for (int r = 0; r < 8; r++) {
        int m = m0 + (ty << 3) + r;
        int t = m & (T_STEPS - 1), b = m >> 12;
        float* dst = C + (size_t)(t * BATCH + b) * GATES + n0 + (tx << 3);
        union { unsigned long long u; float f[2]; } U;
        float o[8];
#pragma unroll
        for (int c4 = 0; c4 < 4; c4++) {
            U.u = acc2[r][c4];
            o[2 * c4 + 0] = U.f[0] + bi[2 * c4 + 0];
            o[2 * c4 + 1] = U.f[1] + bi[2 * c4 + 1];
        }
        *(float4*)(dst + 0) = *(float4*)&o[0];
        *(float4*)(dst + 4) = *(float4*)&o[4];
    }
}

// ---------------- GEMM 2: out = relu(h_cat) @ W_dense + b (unchanged) ------
__global__ void __launch_bounds__(256) k_gemm_dense(
    const float* __restrict__ W, const float* __restrict__ bias,
    float* __restrict__ out)
{
    __shared__ float As[8][128];
    __shared__ float Bs[8][128];
    const int tid = threadIdx.x;
    const int n0 = blockIdx.x << 7, m0 = blockIdx.y << 7;
    const int am = tid >> 1, ak = (tid & 1) << 2;
    const int bk = tid >> 5, bn = (tid & 31) << 2;
    const int ty = tid >> 4, tx = tid & 15;
    unsigned long long acc2[8][4] = {};

    for (int k0 = 0; k0 < 2 * HID; k0 += 8) {
        float4 av = *(const float4*)(g_houts + (size_t)(m0 + am) * (2 * HID) + k0 + ak);
        av.x = fmaxf(av.x, 0.f); av.y = fmaxf(av.y, 0.f);
        av.z = fmaxf(av.z, 0.f); av.w = fmaxf(av.w, 0.f);
        float4 bv = *(const float4*)(W + (size_t)(k0 + bk) * OUTD + n0 + bn);
        __syncthreads();
        As[ak + 0][am] = av.x; As[ak + 1][am] = av.y;
        As[ak + 2][am] = av.z; As[ak + 3][am] = av.w;
        *(float4*)&Bs[bk][bn] = bv;
        __syncthreads();
#pragma unroll
        for (int kk = 0; kk < 8; kk++) {
            float ar[8];
            *(float4*)&ar[0] = *(const float4*)&As[kk][(ty << 3) + 0];
            *(float4*)&ar[4] = *(const float4*)&As[kk][(ty << 3) + 4];
            union { float4 f; unsigned long long u[2]; } B0, B1;
            B0.f = *(const float4*)&Bs[kk][(tx << 3) + 0];
            B1.f = *(const float4*)&Bs[kk][(tx << 3) + 4];
#pragma unroll
            for (int r = 0; r < 8; r++) {
                unsigned long long a2 = bcast2(ar[r]);
                acc2[r][0] = ffma2(a2, B0.u[0], acc2[r][0]);
                acc2[r][1] = ffma2(a2, B0.u[1], acc2[r][1]);
                acc2[r][2] = ffma2(a2, B1.u[0], acc2[r][2]);
                acc2[r][3] = ffma2(a2, B1.u[1], acc2[r][3]);
            }
        }
    }
    float bi[8];
    *(float4*)&bi[0] = *(const float4*)(bias + n0 + (tx << 3) + 0);
    *(float4*)&bi[4] = *(const float4*)(bias + n0 + (tx << 3) + 4);
#pragma unroll
    for (int r = 0; r < 8; r++) {
        int m = m0 + (ty << 3) + r;
        int b = m & 31, t = m >> 5;
        float* dst = out + ((size_t)b * T_STEPS + t) * OUTD + n0 + (tx << 3);
        union { unsigned long long u; float f[2]; } U;
        float o[8];
#pragma unroll
        for (int c4 = 0; c4 < 4; c4++) {
            U.u = acc2[r][c4];
            o[2 * c4 + 0] = U.f[0] + bi[2 * c4 + 0];
            o[2 * c4 + 1] = U.f[1] + bi[2 * c4 + 1];
        }
        *(float4*)(dst + 0) = *(float4*)&o[0];
        *(float4*)(dst + 4) = *(float4*)&o[4];
    }
}

// ---------------- Recurrence: R10 protocol + busy-burn waits ---------------
// Identical to the 22.9ms-best kernel EXCEPT the mbarrier wait busy-polls
// with an FMA burn instead of HW-sleeping, to hold the DVFS boost clock.
__global__ void __cluster_dims__(CL_SZ, 1, 1) __launch_bounds__(512, 1) k_recur(
    const float* __restrict__ carry_c, const float* __restrict__ carry_h,
    const float* __restrict__ Wh_f, const float* __restrict__ Wh_b)
{
    __shared__ float h_s[2][2][HID];           // ping-pong: 2048 B apart
    __shared__ float p_s[4][2][128];
    __shared__ unsigned long long mb[2];       // 8 B apart

    const int tid   = threadIdx.x;
    const int rank  = blockIdx.x & (CL_SZ - 1);
    const int b0    = (blockIdx.x >> 3) << 1;
    const int jbase = rank << 5;

    const int kseg = tid >> 7;
    const int col  = tid & 127;
    const int gate = col >> 5, jl = col & 31;
    const int gc   = (gate << 8) + jbase + jl;

    const bool isprod = (tid >= 448);          // warps 14-15
    const int  pt = tid - 448;
    const int  bp = pt >> 5, jp = pt & 31;
    const unsigned TXB = CL_SZ * 64u * 4u;     // 2048 bytes per exchange

    float bf[4] = {1.0f, 1.1f, 0.9f, 1.05f};   // burn registers

    h_s[0][tid >> 8][tid & 255] =
        carry_h[(size_t)(b0 + (tid >> 8)) * HID + (tid & 255)];

    if (tid == 0) {
        asm volatile("mbarrier.init.shared.b64 [%0], %1;"
                     :: "r"(smem_u32(&mb[0])), "r"(1) : "memory");
        asm volatile("mbarrier.init.shared.b64 [%0], %1;"
                     :: "r"(smem_u32(&mb[1])), "r"(1) : "memory");
    }

    float c_reg = 0.f;
    unsigned rem_h0[CL_SZ];   // peer addr of h_s[0][bp][jbase+jp]; buf1 = +2048
    unsigned rem_mb0[CL_SZ];  // peer addr of mb[0]; mb[1] = +8
    if (isprod) {
        c_reg = carry_c[(size_t)(b0 + bp) * HID + jbase + jp];
        unsigned lh = smem_u32(&h_s[0][bp][jbase + jp]);
        unsigned lm = smem_u32(&mb[0]);
#pragma unroll
        for (int p = 0; p < CL_SZ; p++) {
            asm("mapa.shared::cluster.u32 %0, %1, %2;"
                : "=r"(rem_h0[p]) : "r"(lh), "r"(p));
            asm("mapa.shared::cluster.u32 %0, %1, %2;"
                : "=r"(rem_mb0[p]) : "r"(lm), "r"(p));
        }
    }
    __syncthreads();
    CLUSTER_SYNC();   // mbars + h bufs visible cluster-wide before step 0

    const unsigned mb0a = smem_u32(&mb[0]);

    int gs = 0;
    for (int dir = 0; dir < 2; dir++) {
        const float* __restrict__ Wh = dir ? Wh_b : Wh_f;
        const float* __restrict__ xz = dir ? g_xz_b : g_xz_f;
        const int half = dir ? HID : 0;

        unsigned long long w2[32];
#pragma unroll
        for (int kk = 0; kk < 32; kk++) {
            union { float f[2]; unsigned long long u; } P;
            P.f[0] = Wh[(size_t)((kseg << 6) + 2 * kk + 0) * GATES + gc];
            P.f[1] = Wh[(size_t)((kseg << 6) + 2 * kk + 1) * GATES + gc];
            w2[kk] = P.u;
        }

        float xzp[4];
        if (isprod) {
            const int t0 = dir ? (T_STEPS - 1) : 0;
#pragma unroll
            for (int g = 0; g < 4; g++)
                xzp[g] = __ldcg(xz + ((size_t)t0 * BATCH + b0 + bp) * GATES
                                   + (g << 8) + jbase + jp);
        }

        for (int s = 0; s < T_STEPS; s++, gs++) {
            const int t   = dir ? (T_STEPS - 1 - s) : s;
            const int cur = gs & 1, nxt = cur ^ 1;

            if (gs > 0) {   // wait for exchange gs-1 (all 2048 B landed)
                const int e = gs - 1;
                mbar_wait_burn(mb0a + (unsigned)((e & 1) << 3),
                               (unsigned)((e >> 1) & 1), bf);
            }
            // declare this step's expected exchange bytes (one thread)
            if (tid == 448)
                asm volatile(
                    "mbarrier.arrive.expect_tx.shared.b64 _, [%0], %1;"
                    :: "r"(mb0a + (unsigned)((gs & 1) << 3)), "r"(TXB)
                    : "memory");

            unsigned long long a0 = 0ull, a1 = 0ull;
            {
                const float4* h0 = (const float4*)&h_s[cur][0][kseg << 6];
                const float4* h1 = (const float4*)&h_s[cur][1][kseg << 6];
#pragma unroll
                for (int q = 0; q < 16; q++) {
                    union { float4 f; unsigned long long u[2]; } U0, U1;
                    U0.f = h0[q]; U1.f = h1[q];
                    a0 = ffma2(U0.u[0], w2[2 * q + 0], a0);
                    a0 = ffma2(U0.u[1], w2[2 * q + 1], a0);
                    a1 = ffma2(U1.u[0], w2[2 * q + 0], a1);
                    a1 = ffma2(U1.u[1], w2[2 * q + 1], a1);
                }
            }
            {
                union { unsigned long long u; float f[2]; } A0, A1;
                A0.u = a0; A1.u = a1;
                p_s[kseg][0][col] = A0.f[0] + A0.f[1];
                p_s[kseg][1][col] = A1.f[0] + A1.f[1];
            }
            __syncthreads();

            if (isprod) {
                float z[4];
#pragma unroll
                for (int g = 0; g < 4; g++) {
                    const int cc = (g << 5) + jp;
                    z[g] = xzp[g] + p_s[0][bp][cc] + p_s[1][bp][cc]
                                  + p_s[2][bp][cc] + p_s[3][bp][cc];
                }
                c_reg = fmaf(sigf(z[1]), c_reg, sigf(z[0]) * tanhf_(z[2]));
                const float h = sigf(z[3]) * tanhf_(c_reg);
                const unsigned hoff = (unsigned)(nxt << 11);     // buf stride 2048B
                const unsigned moff = (unsigned)((gs & 1) << 3); // mbar stride 8B
#pragma unroll
                for (int p = 0; p < CL_SZ; p++) {
                    asm volatile(
                        "st.async.shared::cluster.mbarrier::complete_tx::bytes.b32 "
                        "[%0], %1, [%2];"
                        :: "r"(rem_h0[p] + hoff), "r"(__float_as_uint(h)),
                           "r"(rem_mb0[p] + moff) : "memory");
                }
                g_houts[((size_t)t * BATCH + b0 + bp) * (2 * HID)
                        + half + jbase + jp] = h;
                if (s + 1 < T_STEPS) {
                    const int tn = dir ? (T_STEPS - 2 - s) : (s + 1);
#pragma unroll
                    for (int g = 0; g < 4; g++)
                        xzp[g] = __ldcg(xz + ((size_t)tn * BATCH + b0 + bp) * GATES
                                           + (g << 8) + jbase + jp);
                }
            }
            // no second syncthreads: st.async carries data + signal together
        }
    }
    // drain the final exchange so no in-flight st.async targets exiting CTAs
    {
        const int e = 2 * T_STEPS - 1;
        mbar_wait_burn(mb0a + (unsigned)((e & 1) << 3),
                       (unsigned)((e >> 1) & 1), bf);
    }
    asm volatile("" :: "f"(bf[0]), "f"(bf[1]), "f"(bf[2]), "f"(bf[3]));
    CLUSTER_SYNC();
}

// ---------------- launch ----------------------------------------------------
extern "C" void kernel_launch(void* const* d_in, const int* in_sizes, int n_in,
                              void* d_out, int out_size) {
    const float* carry_c = (const float*)d_in[0];
    const float* carry_h = (const float*)d_in[1];
    const float* x       = (const float*)d_in[2];
    const float* Wx_f    = (const float*)d_in[3];
    const float* Wh_f    = (const float*)d_in[4];
    const float* b_f     = (const float*)d_in[5];
    const float* Wx_b    = (const float*)d_in[6];
    const float* Wh_b    = (const float*)d_in[7];
    const float* b_b     = (const float*)d_in[8];
    const float* W_dense = (const float*)d_in[9];
    const float* b_dense = (const float*)d_in[10];
    float* out = (float*)d_out;

    float* xz_f; cudaGetSymbolAddress((void**)&xz_f, g_xz_f);
    float* xz_b; cudaGetSymbolAddress((void**)&xz_b, g_xz_b);

    dim3 g1(GATES / 128, (BATCH * T_STEPS) / 128);
    k_gemm_xz<<<g1, 256>>>(x, Wx_f, b_f, xz_f);
    k_gemm_xz<<<g1, 256>>>(x, Wx_b, b_b, xz_b);

    k_recur<<<NBLK, 512>>>(carry_c, carry_h, Wh_f, Wh_b);

    dim3 g2(OUTD / 128, (BATCH * T_STEPS) / 128);
    k_gemm_dense<<<g2, 256>>>(W_dense, b_dense, out);
}